// round 1
// baseline (speedup 1.0000x reference)
#include <cuda_runtime.h>

#define BB 32
#define NN 128
#define DD 64
#define HH 128
#define NROWS (BB*NN)   // 4096

// ---------------- scratch (device globals; no allocation allowed) ----------------
__device__ float g_AI[BB*NN*HH];   // x @ A1[:d]
__device__ float g_AJ[BB*NN*HH];   // x @ A1[d:] + ab1
__device__ float g_WI[BB*NN*HH];   // x @ W1[:d]
__device__ float g_WJ[BB*NN*HH];   // x @ W1[d:] + b1
__device__ float g_HS[BB*NN*HH];   // sum_j attn * relu(wi+wj)
__device__ float g_SA[BB*NN];      // sum of attn (1.0 or 0.0)
__device__ float g_PWT[16*512*4];  // packed proj weights, [d4][o=g*128+t][4]
__device__ float g_W2T[32*128*4];  // W2 packed [h4][k][4]
__device__ float g_U1T[48*128*4];  // U1 packed [c4][k][4]
__device__ float g_U2T[32*64*4];   // U2 packed [k4][dd][4]

// ---------------- weight repack kernel ----------------
__global__ void prep_kernel(const float* __restrict__ W1, const float* __restrict__ W2,
                            const float* __restrict__ A1, const float* __restrict__ U1,
                            const float* __restrict__ U2) {
    int idx = blockIdx.x * blockDim.x + threadIdx.x;
    int stride = gridDim.x * blockDim.x;
    for (int i = idx; i < 16*512*4; i += stride) {
        int c = i & 3; int o = (i >> 2) & 511; int d4 = i >> 11;
        int g = o >> 7, t = o & 127;
        int row = d4*4 + c + ((g & 1) ? 64 : 0);
        const float* Wsrc = (g < 2) ? A1 : W1;
        g_PWT[i] = Wsrc[row*HH + t];
    }
    for (int i = idx; i < 32*128*4; i += stride) {
        int c = i & 3; int k = (i >> 2) & 127; int h4 = i >> 9;
        g_W2T[i] = W2[(h4*4+c)*HH + k];
    }
    for (int i = idx; i < 48*128*4; i += stride) {
        int c = i & 3; int k = (i >> 2) & 127; int c4 = i >> 9;
        g_U1T[i] = U1[(c4*4+c)*HH + k];
    }
    for (int i = idx; i < 32*64*4; i += stride) {
        int c = i & 3; int dd = (i >> 2) & 63; int k4 = i >> 8;
        g_U2T[i] = U2[(k4*4+c)*DD + dd];
    }
}

// ---------------- per-node projections ----------------
__global__ __launch_bounds__(128)
void proj_kernel(const float* __restrict__ x, const float* __restrict__ b1,
                 const float* __restrict__ ab1) {
    __shared__ __align__(16) float4 xr[16];
    int t = threadIdx.x;
    int row0 = blockIdx.x * 8;
    float biasAJ = ab1[t];
    float biasWJ = b1[t];
    const float4* PW = (const float4*)g_PWT;
    for (int r = 0; r < 8; ++r) {
        int row = row0 + r;
        if (t < 16) xr[t] = ((const float4*)x)[row*16 + t];
        __syncthreads();
        float a0 = 0.f, a1 = 0.f, a2 = 0.f, a3 = 0.f;
        #pragma unroll
        for (int d4 = 0; d4 < 16; ++d4) {
            float4 xv = xr[d4];
            const float4* wp = PW + d4*512 + t;
            float4 w0 = wp[0];
            float4 w1 = wp[128];
            float4 w2 = wp[256];
            float4 w3 = wp[384];
            a0 += xv.x*w0.x + xv.y*w0.y + xv.z*w0.z + xv.w*w0.w;
            a1 += xv.x*w1.x + xv.y*w1.y + xv.z*w1.z + xv.w*w1.w;
            a2 += xv.x*w2.x + xv.y*w2.y + xv.z*w2.z + xv.w*w2.w;
            a3 += xv.x*w3.x + xv.y*w3.y + xv.z*w3.z + xv.w*w3.w;
        }
        g_AI[row*HH + t] = a0;
        g_AJ[row*HH + t] = a1 + biasAJ;
        g_WI[row*HH + t] = a2;
        g_WJ[row*HH + t] = a3 + biasWJ;
        __syncthreads();
    }
}

// ---------------- pairwise attention + weighted-hidden aggregation ----------------
// grid: 512 blocks (32 b x 16 i-tiles of 8), 128 threads.
// smem: tab[128*129] | si[512] | attn[1024] | a2s[128] | wred[32] | msk[128 ints]
#define SMEM_PAIR 73344
__global__ __launch_bounds__(128)
void pair_kernel(const float* __restrict__ A2, const int* __restrict__ masks) {
    extern __shared__ __align__(16) float sm[];
    float* tab  = sm;                 // 16512 floats
    float* si   = tab + 128*129;      // 512
    float* attn = si + 512;           // 1024 (2 quads x 128 j x 4 i)
    float* a2s  = attn + 1024;        // 128
    float* wred = a2s + 128;          // 32: [0..15]=wmax, [16..31]=wsum
    int*   msk  = (int*)(wred + 32);  // 128

    int t = threadIdx.x;
    int b = blockIdx.x >> 4;
    int i0 = (blockIdx.x & 15) * 8;
    int warp = t >> 5, lane = t & 31;

    a2s[t] = A2[t];
    msk[t] = masks[b*NN + t];

    // load AJ transposed: tab[h*129 + j] = AJ[b,j,h]; thread = h, loop j (coalesced LDG, conflict-free STS)
    const float* AJb = g_AJ + b*NN*HH;
    #pragma unroll 4
    for (int j = 0; j < NN; ++j) tab[t*129 + j] = AJb[j*HH + t];

    int cnt = __syncthreads_count(msk[t] != 0);   // barrier + mask population count
    float sa = (cnt > 0) ? 1.0f : 0.0f;
    bool mj = msk[t] != 0;

    // ---- PASS 1: logits + softmax, 2 quads of 4 i each; thread = j ----
    for (int q = 0; q < 2; ++q) {
        {
            const float* AIb = g_AI + (b*NN + i0 + q*4)*HH;
            float4 v;
            v.x = AIb[t]; v.y = AIb[HH + t]; v.z = AIb[2*HH + t]; v.w = AIb[3*HH + t];
            ((float4*)si)[t] = v;
        }
        __syncthreads();
        float l0 = 0.f, l1 = 0.f, l2 = 0.f, l3 = 0.f;
        const float* tp = tab + t;
        #pragma unroll 8
        for (int h = 0; h < HH; ++h) {
            float av = tp[h*129];
            float4 sv = ((const float4*)si)[h];
            float a2v = a2s[h];
            l0 = fmaf(fmaxf(av + sv.x, 0.f), a2v, l0);
            l1 = fmaf(fmaxf(av + sv.y, 0.f), a2v, l1);
            l2 = fmaf(fmaxf(av + sv.z, 0.f), a2v, l2);
            l3 = fmaf(fmaxf(av + sv.w, 0.f), a2v, l3);
        }
        if (!mj) { l0 = l1 = l2 = l3 = -1e30f; }
        // block max (warp shfl + smem)
        float m0 = l0, m1 = l1, m2 = l2, m3 = l3;
        #pragma unroll
        for (int off = 16; off; off >>= 1) {
            m0 = fmaxf(m0, __shfl_xor_sync(0xffffffffu, m0, off));
            m1 = fmaxf(m1, __shfl_xor_sync(0xffffffffu, m1, off));
            m2 = fmaxf(m2, __shfl_xor_sync(0xffffffffu, m2, off));
            m3 = fmaxf(m3, __shfl_xor_sync(0xffffffffu, m3, off));
        }
        if (lane == 0) { wred[warp*4+0]=m0; wred[warp*4+1]=m1; wred[warp*4+2]=m2; wred[warp*4+3]=m3; }
        __syncthreads();
        m0 = fmaxf(fmaxf(wred[0], wred[4]),  fmaxf(wred[8],  wred[12]));
        m1 = fmaxf(fmaxf(wred[1], wred[5]),  fmaxf(wred[9],  wred[13]));
        m2 = fmaxf(fmaxf(wred[2], wred[6]),  fmaxf(wred[10], wred[14]));
        m3 = fmaxf(fmaxf(wred[3], wred[7]),  fmaxf(wred[11], wred[15]));
        float e0 = mj ? __expf(l0 - m0) : 0.f;
        float e1 = mj ? __expf(l1 - m1) : 0.f;
        float e2 = mj ? __expf(l2 - m2) : 0.f;
        float e3 = mj ? __expf(l3 - m3) : 0.f;
        float s0 = e0, s1 = e1, s2 = e2, s3 = e3;
        #pragma unroll
        for (int off = 16; off; off >>= 1) {
            s0 += __shfl_xor_sync(0xffffffffu, s0, off);
            s1 += __shfl_xor_sync(0xffffffffu, s1, off);
            s2 += __shfl_xor_sync(0xffffffffu, s2, off);
            s3 += __shfl_xor_sync(0xffffffffu, s3, off);
        }
        if (lane == 0) { wred[16+warp*4+0]=s0; wred[16+warp*4+1]=s1; wred[16+warp*4+2]=s2; wred[16+warp*4+3]=s3; }
        __syncthreads();
        s0 = wred[16] + wred[20] + wred[24] + wred[28];
        s1 = wred[17] + wred[21] + wred[25] + wred[29];
        s2 = wred[18] + wred[22] + wred[26] + wred[30];
        s3 = wred[19] + wred[23] + wred[27] + wred[31];
        float4 av4;
        av4.x = (cnt > 0) ? e0 / s0 : 0.f;
        av4.y = (cnt > 0) ? e1 / s1 : 0.f;
        av4.z = (cnt > 0) ? e2 / s2 : 0.f;
        av4.w = (cnt > 0) ? e3 / s3 : 0.f;
        ((float4*)attn)[q*128 + t] = av4;
        __syncthreads();
    }

    // ---- load WJ table (plain [j][h], padded) ----
    const float* WJb = g_WJ + b*NN*HH;
    #pragma unroll 4
    for (int j = 0; j < NN; ++j) tab[j*129 + t] = WJb[j*HH + t];
    __syncthreads();

    // ---- PASS 2: weighted hidden sum; thread = h ----
    for (int q = 0; q < 2; ++q) {
        const float* WIb = g_WI + (b*NN + i0 + q*4)*HH;
        float w0 = WIb[t], w1 = WIb[HH + t], w2 = WIb[2*HH + t], w3 = WIb[3*HH + t];
        float h0 = 0.f, h1 = 0.f, h2 = 0.f, h3 = 0.f;
        const float* tp = tab + t;
        #pragma unroll 8
        for (int j = 0; j < NN; ++j) {
            float wv = tp[j*129];
            float4 at = ((const float4*)attn)[q*128 + j];
            h0 = fmaf(at.x, fmaxf(w0 + wv, 0.f), h0);
            h1 = fmaf(at.y, fmaxf(w1 + wv, 0.f), h1);
            h2 = fmaf(at.z, fmaxf(w2 + wv, 0.f), h2);
            h3 = fmaf(at.w, fmaxf(w3 + wv, 0.f), h3);
        }
        float* HSb = g_HS + (b*NN + i0 + q*4)*HH;
        HSb[t] = h0; HSb[HH + t] = h1; HSb[2*HH + t] = h2; HSb[3*HH + t] = h3;
    }
    if (t == 0) {
        #pragma unroll
        for (int r = 0; r < 8; ++r) g_SA[b*NN + i0 + r] = sa;
    }
}

// ---------------- update MLP: agg -> comb -> out ----------------
__global__ __launch_bounds__(128)
void update_kernel(const float* __restrict__ x, const float* __restrict__ b2,
                   const float* __restrict__ ub1, const float* __restrict__ ub2,
                   float* __restrict__ out) {
    __shared__ __align__(16) float hs[128];
    __shared__ __align__(16) float xr[64];
    __shared__ __align__(16) float aggs[128];
    __shared__ __align__(16) float us[128];
    int t = threadIdx.x;
    int row0 = blockIdx.x * 16;
    for (int r = 0; r < 16; ++r) {
        int row = row0 + r;
        hs[t] = g_HS[row*HH + t];
        if (t < 64) xr[t] = x[row*DD + t];
        __syncthreads();
        float sa = g_SA[row];
        // agg = hsum @ W2 + b2*sa
        float acc = b2[t] * sa;
        #pragma unroll
        for (int h4 = 0; h4 < 32; ++h4) {
            float4 hv = ((const float4*)hs)[h4];
            float4 wv = ((const float4*)g_W2T)[h4*128 + t];
            acc += hv.x*wv.x + hv.y*wv.y + hv.z*wv.z + hv.w*wv.w;
        }
        aggs[t] = acc;
        __syncthreads();
        // u = relu([x, agg] @ U1 + ub1)
        float u = ub1[t];
        #pragma unroll
        for (int c4 = 0; c4 < 48; ++c4) {
            float4 cv = (c4 < 16) ? ((const float4*)xr)[c4] : ((const float4*)aggs)[c4 - 16];
            float4 wv = ((const float4*)g_U1T)[c4*128 + t];
            u += cv.x*wv.x + cv.y*wv.y + cv.z*wv.z + cv.w*wv.w;
        }
        us[t] = fmaxf(u, 0.f);
        __syncthreads();
        // out = x + u @ U2 + ub2
        if (t < 64) {
            float o = ub2[t];
            #pragma unroll
            for (int k4 = 0; k4 < 32; ++k4) {
                float4 uv = ((const float4*)us)[k4];
                float4 wv = ((const float4*)g_U2T)[k4*64 + t];
                o += uv.x*wv.x + uv.y*wv.y + uv.z*wv.z + uv.w*wv.w;
            }
            out[row*DD + t] = x[row*DD + t] + o;
        }
        __syncthreads();
    }
}

// ---------------- launch ----------------
extern "C" void kernel_launch(void* const* d_in, const int* in_sizes, int n_in,
                              void* d_out, int out_size) {
    const float* x    = (const float*)d_in[0];
    const int*   masks= (const int*)  d_in[1];
    const float* W1   = (const float*)d_in[2];
    const float* b1   = (const float*)d_in[3];
    const float* W2   = (const float*)d_in[4];
    const float* b2   = (const float*)d_in[5];
    const float* A1   = (const float*)d_in[6];
    const float* ab1  = (const float*)d_in[7];
    const float* A2   = (const float*)d_in[8];
    // d_in[9] = ab2: constant shift, cancels in softmax — unused
    const float* U1   = (const float*)d_in[10];
    const float* ub1  = (const float*)d_in[11];
    const float* U2   = (const float*)d_in[12];
    const float* ub2  = (const float*)d_in[13];
    float* out = (float*)d_out;

    cudaFuncSetAttribute(pair_kernel, cudaFuncAttributeMaxDynamicSharedMemorySize, SMEM_PAIR);

    prep_kernel<<<64, 256>>>(W1, W2, A1, U1, U2);
    proj_kernel<<<NROWS/8, 128>>>(x, b1, ab1);
    pair_kernel<<<BB*16, 128, SMEM_PAIR>>>(A2, masks);
    update_kernel<<<NROWS/16, 128>>>(x, b2, ub1, ub2, out);
}

// round 2
// speedup vs baseline: 2.2558x; 2.2558x over previous
#include <cuda_runtime.h>

#define BB 32
#define NN 128
#define DD 64
#define HH 128
#define NROWS (BB*NN)   // 4096

// ---------------- scratch (device globals) ----------------
__device__ float g_AI[BB*NN*HH];   // x @ A1[:d]
__device__ float g_AJ[BB*NN*HH];   // x @ A1[d:] + ab1
__device__ float g_WI[BB*NN*HH];   // x @ W1[:d]
__device__ float g_WJ[BB*NN*HH];   // x @ W1[d:] + b1
__device__ float g_HS[BB*NN*HH];   // sum_j attn * relu(wi+wj)
__device__ float g_SA[BB*NN];      // sum of attn (1.0 or 0.0)
__device__ float g_PWT[16*512*4];  // packed proj weights, [d4][o=g*128+t][4]
__device__ float g_W2T[32*128*4];  // W2 packed [h4][k][4]
__device__ float g_U1T[48*128*4];  // U1 packed [c4][k][4]
__device__ float g_U2T[32*64*4];   // U2 packed [k4][dd][4]

// ---------------- weight repack ----------------
__global__ void prep_kernel(const float* __restrict__ W1, const float* __restrict__ W2,
                            const float* __restrict__ A1, const float* __restrict__ U1,
                            const float* __restrict__ U2) {
    int idx = blockIdx.x * blockDim.x + threadIdx.x;
    int stride = gridDim.x * blockDim.x;
    for (int i = idx; i < 16*512*4; i += stride) {
        int c = i & 3; int o = (i >> 2) & 511; int d4 = i >> 11;
        int g = o >> 7, t = o & 127;
        int row = d4*4 + c + ((g & 1) ? 64 : 0);
        const float* Wsrc = (g < 2) ? A1 : W1;
        g_PWT[i] = Wsrc[row*HH + t];
    }
    for (int i = idx; i < 32*128*4; i += stride) {
        int c = i & 3; int k = (i >> 2) & 127; int h4 = i >> 9;
        g_W2T[i] = W2[(h4*4+c)*HH + k];
    }
    for (int i = idx; i < 48*128*4; i += stride) {
        int c = i & 3; int k = (i >> 2) & 127; int c4 = i >> 9;
        g_U1T[i] = U1[(c4*4+c)*HH + k];
    }
    for (int i = idx; i < 32*64*4; i += stride) {
        int c = i & 3; int dd = (i >> 2) & 63; int k4 = i >> 8;
        g_U2T[i] = U2[(k4*4+c)*DD + dd];
    }
}

// ---------------- per-node projections (8-row register blocked) ----------------
__global__ __launch_bounds__(128)
void proj_kernel(const float* __restrict__ x, const float* __restrict__ b1,
                 const float* __restrict__ ab1) {
    __shared__ __align__(16) float4 xr[8][16];
    int t = threadIdx.x;
    int row0 = blockIdx.x * 8;
    // load 8 rows of x: 128 float4s, one per thread
    xr[t >> 4][t & 15] = ((const float4*)x)[row0*16 + t];
    __syncthreads();
    float biasAJ = ab1[t];
    float biasWJ = b1[t];
    const float4* PW = (const float4*)g_PWT;
    float a0[8], a1[8], a2[8], a3[8];
    #pragma unroll
    for (int r = 0; r < 8; ++r) { a0[r]=0.f; a1[r]=0.f; a2[r]=0.f; a3[r]=0.f; }
    #pragma unroll 4
    for (int d4 = 0; d4 < 16; ++d4) {
        const float4* wp = PW + d4*512 + t;
        float4 w0 = wp[0];
        float4 w1 = wp[128];
        float4 w2 = wp[256];
        float4 w3 = wp[384];
        #pragma unroll
        for (int r = 0; r < 8; ++r) {
            float4 xv = xr[r][d4];   // broadcast LDS
            a0[r] += xv.x*w0.x + xv.y*w0.y + xv.z*w0.z + xv.w*w0.w;
            a1[r] += xv.x*w1.x + xv.y*w1.y + xv.z*w1.z + xv.w*w1.w;
            a2[r] += xv.x*w2.x + xv.y*w2.y + xv.z*w2.z + xv.w*w2.w;
            a3[r] += xv.x*w3.x + xv.y*w3.y + xv.z*w3.z + xv.w*w3.w;
        }
    }
    #pragma unroll
    for (int r = 0; r < 8; ++r) {
        int row = row0 + r;
        g_AI[row*HH + t] = a0[r];
        g_AJ[row*HH + t] = a1[r] + biasAJ;
        g_WI[row*HH + t] = a2[r];
        g_WJ[row*HH + t] = a3[r] + biasWJ;
    }
}

// ---------------- pairwise attention + aggregation (8-wide i blocking) ----------------
// smem floats: tab 16512 | si 1024 | attn 1024 | a2s 128 | red 128 | msk 128(int)
#define SMEM_PAIR ((16512 + 1024 + 1024 + 128 + 128 + 128) * 4)
__global__ __launch_bounds__(128)
void pair_kernel(const float* __restrict__ A2, const int* __restrict__ masks) {
    extern __shared__ __align__(16) float sm[];
    float* tab  = sm;                 // [h][j] padded 129 (pass1), then [j][h] (pass2)
    float* si   = tab + 128*129;      // [h][8]
    float* attn = si + 1024;          // [j][8]
    float* a2s  = attn + 1024;        // 128
    float* red  = a2s + 128;          // 128: [0..63]=max partials, [64..127]=sum partials
    int*   msk  = (int*)(red + 128);  // 128

    int t = threadIdx.x;
    int b = blockIdx.x >> 4;
    int i0 = (blockIdx.x & 15) * 8;
    int warp = t >> 5, lane = t & 31;

    a2s[t] = A2[t];
    msk[t] = masks[b*NN + t];

    // tab[h=t][j] = AJ[b,j,h=t]
    const float* AJb = g_AJ + b*NN*HH;
    #pragma unroll 4
    for (int j = 0; j < NN; ++j) tab[t*129 + j] = AJb[j*HH + t];

    // si[h=t][ii] = AI[b,i0+ii,h=t]
    const float* AIb = g_AI + (b*NN + i0)*HH;
    #pragma unroll
    for (int ii = 0; ii < 8; ++ii) si[t*8 + ii] = AIb[ii*HH + t];

    int cnt = __syncthreads_count(msk[t] != 0);
    float sa = (cnt > 0) ? 1.0f : 0.0f;
    bool mj = msk[t] != 0;

    // ---- PASS 1: logits for 8 i's; thread = j ----
    float l[8];
    #pragma unroll
    for (int ii = 0; ii < 8; ++ii) l[ii] = 0.f;
    {
        const float* tp = tab + t;
        #pragma unroll 4
        for (int h = 0; h < HH; ++h) {
            float av  = tp[h*129];
            float a2v = a2s[h];
            float4 s0 = *(const float4*)(si + h*8);
            float4 s1 = *(const float4*)(si + h*8 + 4);
            l[0] = fmaf(fmaxf(av + s0.x, 0.f), a2v, l[0]);
            l[1] = fmaf(fmaxf(av + s0.y, 0.f), a2v, l[1]);
            l[2] = fmaf(fmaxf(av + s0.z, 0.f), a2v, l[2]);
            l[3] = fmaf(fmaxf(av + s0.w, 0.f), a2v, l[3]);
            l[4] = fmaf(fmaxf(av + s1.x, 0.f), a2v, l[4]);
            l[5] = fmaf(fmaxf(av + s1.y, 0.f), a2v, l[5]);
            l[6] = fmaf(fmaxf(av + s1.z, 0.f), a2v, l[6]);
            l[7] = fmaf(fmaxf(av + s1.w, 0.f), a2v, l[7]);
        }
    }
    if (!mj) {
        #pragma unroll
        for (int ii = 0; ii < 8; ++ii) l[ii] = -1e30f;
    }
    // block-wide max per i
    float m[8];
    #pragma unroll
    for (int ii = 0; ii < 8; ++ii) {
        float v = l[ii];
        #pragma unroll
        for (int off = 16; off; off >>= 1) v = fmaxf(v, __shfl_xor_sync(0xffffffffu, v, off));
        m[ii] = v;
    }
    if (lane == 0) {
        #pragma unroll
        for (int ii = 0; ii < 8; ++ii) red[warp*8 + ii] = m[ii];
    }
    __syncthreads();
    float e[8], s[8];
    #pragma unroll
    for (int ii = 0; ii < 8; ++ii) {
        float mm = fmaxf(fmaxf(red[ii], red[8+ii]), fmaxf(red[16+ii], red[24+ii]));
        e[ii] = mj ? __expf(l[ii] - mm) : 0.f;
    }
    #pragma unroll
    for (int ii = 0; ii < 8; ++ii) {
        float v = e[ii];
        #pragma unroll
        for (int off = 16; off; off >>= 1) v += __shfl_xor_sync(0xffffffffu, v, off);
        s[ii] = v;
    }
    if (lane == 0) {
        #pragma unroll
        for (int ii = 0; ii < 8; ++ii) red[64 + warp*8 + ii] = s[ii];
    }
    __syncthreads();
    #pragma unroll
    for (int ii = 0; ii < 8; ++ii) {
        float ss = red[64+ii] + red[64+8+ii] + red[64+16+ii] + red[64+24+ii];
        float inv = (cnt > 0) ? (1.0f / ss) : 0.f;
        attn[t*8 + ii] = e[ii] * inv;
    }
    __syncthreads();

    // ---- reload table as WJ[j][h] ----
    const float* WJb = g_WJ + b*NN*HH;
    #pragma unroll 4
    for (int j = 0; j < NN; ++j) tab[j*129 + t] = WJb[j*HH + t];
    __syncthreads();

    // ---- PASS 2: weighted hidden sum; thread = h ----
    const float* WIb = g_WI + (b*NN + i0)*HH;
    float wi[8];
    #pragma unroll
    for (int ii = 0; ii < 8; ++ii) wi[ii] = WIb[ii*HH + t];
    float hc[8];
    #pragma unroll
    for (int ii = 0; ii < 8; ++ii) hc[ii] = 0.f;
    {
        const float* tp = tab + t;
        #pragma unroll 4
        for (int j = 0; j < NN; ++j) {
            float wv = tp[j*129];
            float4 a0 = *(const float4*)(attn + j*8);
            float4 a1 = *(const float4*)(attn + j*8 + 4);
            hc[0] = fmaf(a0.x, fmaxf(wi[0] + wv, 0.f), hc[0]);
            hc[1] = fmaf(a0.y, fmaxf(wi[1] + wv, 0.f), hc[1]);
            hc[2] = fmaf(a0.z, fmaxf(wi[2] + wv, 0.f), hc[2]);
            hc[3] = fmaf(a0.w, fmaxf(wi[3] + wv, 0.f), hc[3]);
            hc[4] = fmaf(a1.x, fmaxf(wi[4] + wv, 0.f), hc[4]);
            hc[5] = fmaf(a1.y, fmaxf(wi[5] + wv, 0.f), hc[5]);
            hc[6] = fmaf(a1.z, fmaxf(wi[6] + wv, 0.f), hc[6]);
            hc[7] = fmaf(a1.w, fmaxf(wi[7] + wv, 0.f), hc[7]);
        }
    }
    float* HSb = g_HS + (b*NN + i0)*HH;
    #pragma unroll
    for (int ii = 0; ii < 8; ++ii) HSb[ii*HH + t] = hc[ii];
    if (t < 8) g_SA[b*NN + i0 + t] = sa;
}

// ---------------- update MLP (8-row register blocked) ----------------
__global__ __launch_bounds__(128)
void update_kernel(const float* __restrict__ x, const float* __restrict__ b2,
                   const float* __restrict__ ub1, const float* __restrict__ ub2,
                   float* __restrict__ out) {
    __shared__ __align__(16) float hs[8*128];
    __shared__ __align__(16) float xr[8*64];
    __shared__ __align__(16) float aggs[8*128];
    __shared__ __align__(16) float us[8*128];
    __shared__ float sa8[8];
    int t = threadIdx.x;
    int row0 = blockIdx.x * 8;

    #pragma unroll
    for (int r = 0; r < 8; ++r) hs[r*128 + t] = g_HS[(row0+r)*HH + t];
    for (int k = t; k < 512; k += 128) {
        int r = k >> 6, c = k & 63;
        xr[k] = x[(row0+r)*DD + c];
    }
    if (t < 8) sa8[t] = g_SA[row0 + t];
    __syncthreads();

    // Phase A: agg[r][t] = hs[r] @ W2[:,t] + b2[t]*sa[r]
    {
        float b2v = b2[t];
        float acc[8];
        #pragma unroll
        for (int r = 0; r < 8; ++r) acc[r] = b2v * sa8[r];
        const float4* W2T4 = (const float4*)g_W2T;
        const float4* hs4 = (const float4*)hs;
        #pragma unroll 4
        for (int h4 = 0; h4 < 32; ++h4) {
            float4 wv = W2T4[h4*128 + t];
            #pragma unroll
            for (int r = 0; r < 8; ++r) {
                float4 hv = hs4[r*32 + h4];   // broadcast LDS
                acc[r] += hv.x*wv.x + hv.y*wv.y + hv.z*wv.z + hv.w*wv.w;
            }
        }
        #pragma unroll
        for (int r = 0; r < 8; ++r) aggs[r*128 + t] = acc[r];
    }
    __syncthreads();

    // Phase B: us[r][t] = relu([x_r, agg_r] @ U1[:,t] + ub1[t])
    {
        float ubv = ub1[t];
        float u[8];
        #pragma unroll
        for (int r = 0; r < 8; ++r) u[r] = ubv;
        const float4* U1T4 = (const float4*)g_U1T;
        const float4* xr4 = (const float4*)xr;
        const float4* ag4 = (const float4*)aggs;
        #pragma unroll 4
        for (int c4 = 0; c4 < 48; ++c4) {
            float4 wv = U1T4[c4*128 + t];
            #pragma unroll
            for (int r = 0; r < 8; ++r) {
                float4 cv = (c4 < 16) ? xr4[r*16 + c4] : ag4[r*32 + (c4-16)];
                u[r] += cv.x*wv.x + cv.y*wv.y + cv.z*wv.z + cv.w*wv.w;
            }
        }
        #pragma unroll
        for (int r = 0; r < 8; ++r) us[r*128 + t] = fmaxf(u[r], 0.f);
    }
    __syncthreads();

    // Phase C: out[r][col] = x[r][col] + us[r] @ U2[:,col] + ub2[col]
    {
        int col = t & 63;
        int rg  = t >> 6;           // 0/1 -> rows rg*4 .. rg*4+3
        float o[4];
        float ub2v = ub2[col];
        #pragma unroll
        for (int rr = 0; rr < 4; ++rr) o[rr] = ub2v;
        const float4* U2T4 = (const float4*)g_U2T;
        const float4* us4 = (const float4*)us;
        #pragma unroll 4
        for (int k4 = 0; k4 < 32; ++k4) {
            float4 wv = U2T4[k4*64 + col];
            #pragma unroll
            for (int rr = 0; rr < 4; ++rr) {
                int r = rg*4 + rr;
                float4 uv = us4[r*32 + k4];   // broadcast within half-warp groups
                o[rr] += uv.x*wv.x + uv.y*wv.y + uv.z*wv.z + uv.w*wv.w;
            }
        }
        #pragma unroll
        for (int rr = 0; rr < 4; ++rr) {
            int r = rg*4 + rr;
            out[(row0+r)*DD + col] = xr[r*64 + col] + o[rr];
        }
    }
}

// ---------------- launch ----------------
extern "C" void kernel_launch(void* const* d_in, const int* in_sizes, int n_in,
                              void* d_out, int out_size) {
    const float* x    = (const float*)d_in[0];
    const int*   masks= (const int*)  d_in[1];
    const float* W1   = (const float*)d_in[2];
    const float* b1   = (const float*)d_in[3];
    const float* W2   = (const float*)d_in[4];
    const float* b2   = (const float*)d_in[5];
    const float* A1   = (const float*)d_in[6];
    const float* ab1  = (const float*)d_in[7];
    const float* A2   = (const float*)d_in[8];
    // d_in[9] = ab2: cancels in softmax
    const float* U1   = (const float*)d_in[10];
    const float* ub1  = (const float*)d_in[11];
    const float* U2   = (const float*)d_in[12];
    const float* ub2  = (const float*)d_in[13];
    float* out = (float*)d_out;

    cudaFuncSetAttribute(pair_kernel, cudaFuncAttributeMaxDynamicSharedMemorySize, SMEM_PAIR);

    prep_kernel<<<64, 256>>>(W1, W2, A1, U1, U2);
    proj_kernel<<<NROWS/8, 128>>>(x, b1, ab1);
    pair_kernel<<<BB*16, 128, SMEM_PAIR>>>(A2, masks);
    update_kernel<<<NROWS/8, 128>>>(x, b2, ub1, ub2, out);
}

// round 3
// speedup vs baseline: 2.5860x; 1.1464x over previous
#include <cuda_runtime.h>

#define BB 32
#define NN 128
#define DD 64
#define HH 128
#define NROWS (BB*NN)   // 4096

// ---------------- scratch (device globals) ----------------
__device__ float g_AI[BB*NN*HH];   // x @ A1[:d]
__device__ float g_AJ[BB*NN*HH];   // x @ A1[d:] + ab1
__device__ float g_WI[BB*NN*HH];   // x @ W1[:d]
__device__ float g_WJ[BB*NN*HH];   // x @ W1[d:] + b1
__device__ float g_PWT[16*512*4];  // packed proj weights, [d4][o=g*128+col][4]
__device__ float g_W2T[32*128*4];  // W2 packed [h4][k][4]
__device__ float g_U1T[48*128*4];  // U1 packed [c4][k][4]
__device__ float g_U2T[32*64*4];   // U2 packed [k4][dd][4]

// ---------------- weight repack ----------------
__global__ void prep_kernel(const float* __restrict__ W1, const float* __restrict__ W2,
                            const float* __restrict__ A1, const float* __restrict__ U1,
                            const float* __restrict__ U2) {
    int idx = blockIdx.x * blockDim.x + threadIdx.x;
    int stride = gridDim.x * blockDim.x;
    for (int i = idx; i < 16*512*4; i += stride) {
        int c = i & 3; int o = (i >> 2) & 511; int d4 = i >> 11;
        int g = o >> 7, t = o & 127;
        int row = d4*4 + c + ((g & 1) ? 64 : 0);
        const float* Wsrc = (g < 2) ? A1 : W1;
        g_PWT[i] = Wsrc[row*HH + t];
    }
    for (int i = idx; i < 32*128*4; i += stride) {
        int c = i & 3; int k = (i >> 2) & 127; int h4 = i >> 9;
        g_W2T[i] = W2[(h4*4+c)*HH + k];
    }
    for (int i = idx; i < 48*128*4; i += stride) {
        int c = i & 3; int k = (i >> 2) & 127; int c4 = i >> 9;
        g_U1T[i] = U1[(c4*4+c)*HH + k];
    }
    for (int i = idx; i < 32*64*4; i += stride) {
        int c = i & 3; int dd = (i >> 2) & 63; int k4 = i >> 8;
        g_U2T[i] = U2[(k4*4+c)*DD + dd];
    }
}

// ---------------- per-node projections (256 thr, 4 rows/thread) ----------------
__global__ __launch_bounds__(256)
void proj_kernel(const float* __restrict__ x, const float* __restrict__ b1,
                 const float* __restrict__ ab1) {
    __shared__ __align__(16) float4 xr[8][16];
    int t = threadIdx.x;
    int col = t & 127;
    int half = t >> 7;
    int row0 = blockIdx.x * 8;
    if (t < 128) xr[t >> 4][t & 15] = ((const float4*)x)[row0*16 + t];
    __syncthreads();
    float biasAJ = ab1[col];
    float biasWJ = b1[col];
    const float4* PW = (const float4*)g_PWT;
    float a0[4], a1[4], a2[4], a3[4];
    #pragma unroll
    for (int k = 0; k < 4; ++k) { a0[k]=0.f; a1[k]=0.f; a2[k]=0.f; a3[k]=0.f; }
    #pragma unroll 4
    for (int d4 = 0; d4 < 16; ++d4) {
        const float4* wp = PW + d4*512 + col;
        float4 w0 = wp[0];
        float4 w1 = wp[128];
        float4 w2 = wp[256];
        float4 w3 = wp[384];
        #pragma unroll
        for (int k = 0; k < 4; ++k) {
            float4 xv = xr[half*4 + k][d4];   // broadcast LDS
            a0[k] += xv.x*w0.x + xv.y*w0.y + xv.z*w0.z + xv.w*w0.w;
            a1[k] += xv.x*w1.x + xv.y*w1.y + xv.z*w1.z + xv.w*w1.w;
            a2[k] += xv.x*w2.x + xv.y*w2.y + xv.z*w2.z + xv.w*w2.w;
            a3[k] += xv.x*w3.x + xv.y*w3.y + xv.z*w3.z + xv.w*w3.w;
        }
    }
    #pragma unroll
    for (int k = 0; k < 4; ++k) {
        int row = row0 + half*4 + k;
        g_AI[row*HH + col] = a0[k];
        g_AJ[row*HH + col] = a1[k] + biasAJ;
        g_WI[row*HH + col] = a2[k];
        g_WJ[row*HH + col] = a3[k] + biasWJ;
    }
}

// ---------------- fused pair + update kernel ----------------
// 512 blocks (32 b x 16 i-tiles of 8), 256 threads.
// SMEM floats:
//   tab : [0, 16512)        pass1 [h][j] / pass2 [j][h] (stride 129);
//                           after pass2 reused: xr=tab[0..512), aggs=tab[512..1536), us=tab[1536..2560)
//   hsb : [16512, 17536)    pass1 si [h][8]  ->  pass2 output hs [r][128]
//   attn: [17536, 18560)    [j][8]
//   a2s : [18560, 18688)
//   red : [18688, 18816)
//   msk : [18816, 18944)    ints
#define SMF_FLOATS 18944
#define SMEM_FUSED (SMF_FLOATS * 4)
__global__ __launch_bounds__(256)
void fused_kernel(const float* __restrict__ x, const float* __restrict__ A2,
                  const int* __restrict__ masks,
                  const float* __restrict__ b2, const float* __restrict__ ub1,
                  const float* __restrict__ ub2, float* __restrict__ out) {
    extern __shared__ __align__(16) float sm[];
    float* tab  = sm;
    float* hsb  = sm + 16512;   // si during pass1, hs after pass2
    float* attn = sm + 17536;
    float* a2s  = sm + 18560;
    float* red  = sm + 18688;
    int*   msk  = (int*)(sm + 18816);

    int t = threadIdx.x;
    int c128 = t & 127;
    int half = t >> 7;          // 0/1
    int warp = t >> 5, lane = t & 31;
    int b  = blockIdx.x >> 4;
    int i0 = (blockIdx.x & 15) * 8;
    int rowbase = b*NN + i0;

    // preload x tile into registers (8 rows x 64 = 512 floats)
    float xreg0 = x[rowbase*DD + t];
    float xreg1 = x[rowbase*DD + 256 + t];

    if (t < 128) { a2s[t] = A2[t]; msk[t] = masks[b*NN + t]; }

    // tab[h=c128][j] = AJ[b,j,h]; each half loads 64 j's (coalesced LDG, conflict-free STS)
    const float* AJb = g_AJ + b*NN*HH;
    #pragma unroll 4
    for (int jj = 0; jj < 64; ++jj) {
        int j = half*64 + jj;
        tab[c128*129 + j] = AJb[j*HH + c128];
    }
    // si[h=c128][ii] for this half's 4 i's
    const float* AIb = g_AI + rowbase*HH;
    #pragma unroll
    for (int k = 0; k < 4; ++k)
        hsb[c128*8 + half*4 + k] = AIb[(half*4 + k)*HH + c128];

    int cnt = __syncthreads_count(msk[c128] != 0);
    float sa = (cnt > 0) ? 1.0f : 0.0f;
    bool mj = msk[c128] != 0;

    // ---- PASS 1: logits for this half's 4 i's; thread = j (= c128) ----
    float l[4];
    #pragma unroll
    for (int k = 0; k < 4; ++k) l[k] = 0.f;
    {
        const float* tp = tab + c128;
        const float* sp = hsb + half*4;
        #pragma unroll 4
        for (int h = 0; h < HH; ++h) {
            float av  = tp[h*129];
            float a2v = a2s[h];
            float4 sv = *(const float4*)(sp + h*8);
            l[0] = fmaf(fmaxf(av + sv.x, 0.f), a2v, l[0]);
            l[1] = fmaf(fmaxf(av + sv.y, 0.f), a2v, l[1]);
            l[2] = fmaf(fmaxf(av + sv.z, 0.f), a2v, l[2]);
            l[3] = fmaf(fmaxf(av + sv.w, 0.f), a2v, l[3]);
        }
    }
    if (!mj) {
        #pragma unroll
        for (int k = 0; k < 4; ++k) l[k] = -1e30f;
    }
    // block-max per i (reduce over j within each half: 4 warps)
    {
        float m[4];
        #pragma unroll
        for (int k = 0; k < 4; ++k) {
            float v = l[k];
            #pragma unroll
            for (int off = 16; off; off >>= 1) v = fmaxf(v, __shfl_xor_sync(0xffffffffu, v, off));
            m[k] = v;
        }
        if (lane == 0) {
            #pragma unroll
            for (int k = 0; k < 4; ++k) red[warp*4 + k] = m[k];
        }
    }
    __syncthreads();
    float e[4];
    {
        int rb = half*16;
        #pragma unroll
        for (int k = 0; k < 4; ++k) {
            float mm = fmaxf(fmaxf(red[rb + k], red[rb + 4 + k]),
                             fmaxf(red[rb + 8 + k], red[rb + 12 + k]));
            e[k] = mj ? __expf(l[k] - mm) : 0.f;
        }
        float s[4];
        #pragma unroll
        for (int k = 0; k < 4; ++k) {
            float v = e[k];
            #pragma unroll
            for (int off = 16; off; off >>= 1) v += __shfl_xor_sync(0xffffffffu, v, off);
            s[k] = v;
        }
        if (lane == 0) {
            #pragma unroll
            for (int k = 0; k < 4; ++k) red[64 + warp*4 + k] = s[k];
        }
    }
    __syncthreads();
    {
        int rb = 64 + half*16;
        #pragma unroll
        for (int k = 0; k < 4; ++k) {
            float ss = red[rb + k] + red[rb + 4 + k] + red[rb + 8 + k] + red[rb + 12 + k];
            float inv = (cnt > 0) ? (1.0f / ss) : 0.f;
            attn[c128*8 + half*4 + k] = e[k] * inv;
        }
    }
    __syncthreads();

    // ---- reload table as WJ[j][h] ----
    const float* WJb = g_WJ + b*NN*HH;
    #pragma unroll 4
    for (int jj = 0; jj < 64; ++jj) {
        int j = half*64 + jj;
        tab[j*129 + c128] = WJb[j*HH + c128];
    }
    __syncthreads();

    // ---- PASS 2: weighted hidden sum; thread = h (= c128), 4 i's per thread ----
    {
        const float* WIb = g_WI + rowbase*HH;
        float wi[4], hc[4];
        #pragma unroll
        for (int k = 0; k < 4; ++k) {
            wi[k] = WIb[(half*4 + k)*HH + c128];
            hc[k] = 0.f;
        }
        const float* tp = tab + c128;
        const float* ap = attn + half*4;
        #pragma unroll 4
        for (int j = 0; j < NN; ++j) {
            float wv = tp[j*129];
            float4 at = *(const float4*)(ap + j*8);
            hc[0] = fmaf(at.x, fmaxf(wi[0] + wv, 0.f), hc[0]);
            hc[1] = fmaf(at.y, fmaxf(wi[1] + wv, 0.f), hc[1]);
            hc[2] = fmaf(at.z, fmaxf(wi[2] + wv, 0.f), hc[2]);
            hc[3] = fmaf(at.w, fmaxf(wi[3] + wv, 0.f), hc[3]);
        }
        // hs[r][h] into hsb (si region: dead after pass1)
        #pragma unroll
        for (int k = 0; k < 4; ++k) hsb[(half*4 + k)*128 + c128] = hc[k];
    }
    __syncthreads();   // tab is now free; hs complete

    // ---- UPDATE phases (overlay xr/aggs/us onto tab) ----
    float* xr   = tab;          // 512 floats [r][64]
    float* aggs = tab + 512;    // 1024 floats [r][128]
    float* us   = tab + 1536;   // 1024 floats [r][128]

    xr[t] = xreg0;
    xr[256 + t] = xreg1;

    // Phase A: agg[r][col] = hs[r] @ W2[:,col] + b2[col]*sa   (4 rows/thread)
    {
        float b2v = b2[c128];
        float acc[4];
        #pragma unroll
        for (int k = 0; k < 4; ++k) acc[k] = b2v * sa;
        const float4* W2T4 = (const float4*)g_W2T;
        const float4* hs4  = (const float4*)hsb;
        #pragma unroll 4
        for (int h4 = 0; h4 < 32; ++h4) {
            float4 wv = W2T4[h4*128 + c128];
            #pragma unroll
            for (int k = 0; k < 4; ++k) {
                float4 hv = hs4[(half*4 + k)*32 + h4];   // broadcast LDS
                acc[k] += hv.x*wv.x + hv.y*wv.y + hv.z*wv.z + hv.w*wv.w;
            }
        }
        #pragma unroll
        for (int k = 0; k < 4; ++k) aggs[(half*4 + k)*128 + c128] = acc[k];
    }
    __syncthreads();

    // Phase B: us[r][col] = relu([x_r, agg_r] @ U1[:,col] + ub1[col])
    {
        float ubv = ub1[c128];
        float u[4];
        #pragma unroll
        for (int k = 0; k < 4; ++k) u[k] = ubv;
        const float4* U1T4 = (const float4*)g_U1T;
        const float4* xr4  = (const float4*)xr;
        const float4* ag4  = (const float4*)aggs;
        #pragma unroll 4
        for (int c4 = 0; c4 < 48; ++c4) {
            float4 wv = U1T4[c4*128 + c128];
            #pragma unroll
            for (int k = 0; k < 4; ++k) {
                int r = half*4 + k;
                float4 cv = (c4 < 16) ? xr4[r*16 + c4] : ag4[r*32 + (c4-16)];
                u[k] += cv.x*wv.x + cv.y*wv.y + cv.z*wv.z + cv.w*wv.w;
            }
        }
        #pragma unroll
        for (int k = 0; k < 4; ++k) us[(half*4 + k)*128 + c128] = fmaxf(u[k], 0.f);
    }
    __syncthreads();

    // Phase C: out[r][col] = x[r][col] + us[r] @ U2[:,col] + ub2[col]  (2 rows/thread)
    {
        int col = t & 63;
        int rq  = t >> 6;            // 0..3 -> rows rq*2, rq*2+1
        float ub2v = ub2[col];
        float o0 = ub2v, o1 = ub2v;
        const float4* U2T4 = (const float4*)g_U2T;
        const float4* us4  = (const float4*)us;
        #pragma unroll 4
        for (int k4 = 0; k4 < 32; ++k4) {
            float4 wv = U2T4[k4*64 + col];
            float4 u0 = us4[(rq*2    )*32 + k4];   // broadcast
            float4 u1 = us4[(rq*2 + 1)*32 + k4];
            o0 += u0.x*wv.x + u0.y*wv.y + u0.z*wv.z + u0.w*wv.w;
            o1 += u1.x*wv.x + u1.y*wv.y + u1.z*wv.z + u1.w*wv.w;
        }
        int r0 = rq*2;
        out[(rowbase + r0    )*DD + col] = xr[r0*64 + col] + o0;
        out[(rowbase + r0 + 1)*DD + col] = xr[(r0+1)*64 + col] + o1;
    }
}

// ---------------- launch ----------------
extern "C" void kernel_launch(void* const* d_in, const int* in_sizes, int n_in,
                              void* d_out, int out_size) {
    const float* x    = (const float*)d_in[0];
    const int*   masks= (const int*)  d_in[1];
    const float* W1   = (const float*)d_in[2];
    const float* b1   = (const float*)d_in[3];
    const float* W2   = (const float*)d_in[4];
    const float* b2   = (const float*)d_in[5];
    const float* A1   = (const float*)d_in[6];
    const float* ab1  = (const float*)d_in[7];
    const float* A2   = (const float*)d_in[8];
    // d_in[9] = ab2: cancels in softmax
    const float* U1   = (const float*)d_in[10];
    const float* ub1  = (const float*)d_in[11];
    const float* U2   = (const float*)d_in[12];
    const float* ub2  = (const float*)d_in[13];
    float* out = (float*)d_out;

    cudaFuncSetAttribute(fused_kernel, cudaFuncAttributeMaxDynamicSharedMemorySize, SMEM_FUSED);

    prep_kernel<<<64, 256>>>(W1, W2, A1, U1, U2);
    proj_kernel<<<NROWS/8, 256>>>(x, b1, ab1);
    fused_kernel<<<BB*16, 256, SMEM_FUSED>>>(x, A2, masks, b2, ub1, ub2, out);
}

// round 4
// speedup vs baseline: 2.8889x; 1.1171x over previous
#include <cuda_runtime.h>

#define BB 32
#define NN 128
#define DD 64
#define HH 128
#define NROWS (BB*NN)   // 4096

// ---------------- scratch (device globals) ----------------
__device__ float g_AI[BB*NN*HH];   // x @ A1[:d]
__device__ float g_AJ[BB*NN*HH];   // x @ A1[d:] + ab1
__device__ float g_WI[BB*NN*HH];   // x @ W1[:d]
__device__ float g_WJ[BB*NN*HH];   // x @ W1[d:] + b1
__device__ float g_PWT[16*512*4];  // packed proj weights, [d4][o=g*128+col][4]
__device__ float g_W2T[32*128*4];  // W2 packed [h4][k][4]
__device__ float g_U1T[48*128*4];  // U1 packed [c4][k][4]
__device__ float g_U2T[32*64*4];   // U2 packed [k4][dd][4]

// ---------------- weight repack ----------------
__global__ void prep_kernel(const float* __restrict__ W1, const float* __restrict__ W2,
                            const float* __restrict__ A1, const float* __restrict__ U1,
                            const float* __restrict__ U2) {
    int idx = blockIdx.x * blockDim.x + threadIdx.x;
    int stride = gridDim.x * blockDim.x;
    for (int i = idx; i < 16*512*4; i += stride) {
        int c = i & 3; int o = (i >> 2) & 511; int d4 = i >> 11;
        int g = o >> 7, t = o & 127;
        int row = d4*4 + c + ((g & 1) ? 64 : 0);
        const float* Wsrc = (g < 2) ? A1 : W1;
        g_PWT[i] = Wsrc[row*HH + t];
    }
    for (int i = idx; i < 32*128*4; i += stride) {
        int c = i & 3; int k = (i >> 2) & 127; int h4 = i >> 9;
        g_W2T[i] = W2[(h4*4+c)*HH + k];
    }
    for (int i = idx; i < 48*128*4; i += stride) {
        int c = i & 3; int k = (i >> 2) & 127; int c4 = i >> 9;
        g_U1T[i] = U1[(c4*4+c)*HH + k];
    }
    for (int i = idx; i < 32*64*4; i += stride) {
        int c = i & 3; int dd = (i >> 2) & 63; int k4 = i >> 8;
        g_U2T[i] = U2[(k4*4+c)*DD + dd];
    }
}

// ---------------- per-node projections (256 thr, 4 rows/thread) ----------------
__global__ __launch_bounds__(256)
void proj_kernel(const float* __restrict__ x, const float* __restrict__ b1,
                 const float* __restrict__ ab1) {
    __shared__ __align__(16) float4 xr[8][16];
    int t = threadIdx.x;
    int col = t & 127;
    int half = t >> 7;
    int row0 = blockIdx.x * 8;
    if (t < 128) xr[t >> 4][t & 15] = ((const float4*)x)[row0*16 + t];
    __syncthreads();
    float biasAJ = ab1[col];
    float biasWJ = b1[col];
    const float4* PW = (const float4*)g_PWT;
    float a0[4], a1[4], a2[4], a3[4];
    #pragma unroll
    for (int k = 0; k < 4; ++k) { a0[k]=0.f; a1[k]=0.f; a2[k]=0.f; a3[k]=0.f; }
    #pragma unroll 4
    for (int d4 = 0; d4 < 16; ++d4) {
        const float4* wp = PW + d4*512 + col;
        float4 w0 = wp[0];
        float4 w1 = wp[128];
        float4 w2 = wp[256];
        float4 w3 = wp[384];
        #pragma unroll
        for (int k = 0; k < 4; ++k) {
            float4 xv = xr[half*4 + k][d4];   // broadcast LDS
            a0[k] += xv.x*w0.x + xv.y*w0.y + xv.z*w0.z + xv.w*w0.w;
            a1[k] += xv.x*w1.x + xv.y*w1.y + xv.z*w1.z + xv.w*w1.w;
            a2[k] += xv.x*w2.x + xv.y*w2.y + xv.z*w2.z + xv.w*w2.w;
            a3[k] += xv.x*w3.x + xv.y*w3.y + xv.z*w3.z + xv.w*w3.w;
        }
    }
    #pragma unroll
    for (int k = 0; k < 4; ++k) {
        int row = row0 + half*4 + k;
        g_AI[row*HH + col] = a0[k];
        g_AJ[row*HH + col] = a1[k] + biasAJ;
        g_WI[row*HH + col] = a2[k];
        g_WJ[row*HH + col] = a3[k] + biasWJ;
    }
}

// ---------------- fused pair + update kernel (h-chunked table, 42KB smem) ----------------
// 512 blocks (32 b x 16 i-tiles of 8), 256 threads, >=4 blocks/SM -> single wave.
// SMEM floats:
//   tab : [0, 8320)       [j=128][hl] stride 65 (h-chunk of AJ / WJ);
//                         after pass2 reused: xr[0..512) aggs[512..1536) us[1536..2560)
//   hsb : [8320, 9344)    pass1 aiT [h][8]  ->  pass2 output hs [r][128]
//   attn: [9344, 10368)   [j][8]
//   a2s : [10368, 10496)
//   red : [10496, 10624)
//   msk : [10624, 10752)  ints
#define SMF_FLOATS 10752
#define SMEM_FUSED (SMF_FLOATS * 4)
__global__ __launch_bounds__(256, 4)
void fused_kernel(const float* __restrict__ x, const float* __restrict__ A2,
                  const int* __restrict__ masks,
                  const float* __restrict__ b2, const float* __restrict__ ub1,
                  const float* __restrict__ ub2, float* __restrict__ out) {
    extern __shared__ __align__(16) float sm[];
    float* tab  = sm;
    float* hsb  = sm + 8320;    // aiT during pass1, hs after pass2
    float* attn = sm + 9344;
    float* a2s  = sm + 10368;
    float* red  = sm + 10496;
    int*   msk  = (int*)(sm + 10624);

    int t = threadIdx.x;
    int c128 = t & 127;
    int half = t >> 7;          // 0/1
    int warp = t >> 5, lane = t & 31;
    int b  = blockIdx.x >> 4;
    int i0 = (blockIdx.x & 15) * 8;
    int rowbase = b*NN + i0;

    // preload x tile into registers (8 rows x 64 = 512 floats)
    float xreg0 = x[rowbase*DD + t];
    float xreg1 = x[rowbase*DD + 256 + t];

    if (t < 128) { a2s[t] = A2[t]; msk[t] = masks[b*NN + t]; }

    // aiT[h=c128][ii] for this half's 4 i's
    const float* AIb = g_AI + rowbase*HH;
    #pragma unroll
    for (int k = 0; k < 4; ++k)
        hsb[c128*8 + half*4 + k] = AIb[(half*4 + k)*HH + c128];

    int cnt = __syncthreads_count(msk[c128] != 0);
    float sa = (cnt > 0) ? 1.0f : 0.0f;
    bool mj = msk[c128] != 0;

    // ---- PASS 1: logits over 2 h-chunks; thread = (j=c128, half: 4 i's) ----
    float l[4];
    #pragma unroll
    for (int k = 0; k < 4; ++k) l[k] = 0.f;
    const float* AJb = g_AJ + b*NN*HH;
    #pragma unroll
    for (int c = 0; c < 2; ++c) {
        // load AJ h-chunk: tab[j][hl] = AJ[b,j,c*64+hl]
        #pragma unroll 8
        for (int idx = t; idx < 128*64; idx += 256) {
            int j = idx >> 6, hl = idx & 63;
            tab[j*65 + hl] = AJb[j*HH + c*64 + hl];
        }
        __syncthreads();
        const float* tp = tab + c128*65;
        const float* sp = hsb + c*64*8 + half*4;
        #pragma unroll 4
        for (int hl = 0; hl < 64; ++hl) {
            float av  = tp[hl];
            float a2v = a2s[c*64 + hl];
            float4 sv = *(const float4*)(sp + hl*8);
            l[0] = fmaf(fmaxf(av + sv.x, 0.f), a2v, l[0]);
            l[1] = fmaf(fmaxf(av + sv.y, 0.f), a2v, l[1]);
            l[2] = fmaf(fmaxf(av + sv.z, 0.f), a2v, l[2]);
            l[3] = fmaf(fmaxf(av + sv.w, 0.f), a2v, l[3]);
        }
        __syncthreads();
    }
    if (!mj) {
        #pragma unroll
        for (int k = 0; k < 4; ++k) l[k] = -1e30f;
    }
    // block-max per i (reduce over j within each half: 4 warps)
    {
        float m[4];
        #pragma unroll
        for (int k = 0; k < 4; ++k) {
            float v = l[k];
            #pragma unroll
            for (int off = 16; off; off >>= 1) v = fmaxf(v, __shfl_xor_sync(0xffffffffu, v, off));
            m[k] = v;
        }
        if (lane == 0) {
            #pragma unroll
            for (int k = 0; k < 4; ++k) red[warp*4 + k] = m[k];
        }
    }
    __syncthreads();
    float e[4];
    {
        int rb = half*16;
        #pragma unroll
        for (int k = 0; k < 4; ++k) {
            float mm = fmaxf(fmaxf(red[rb + k], red[rb + 4 + k]),
                             fmaxf(red[rb + 8 + k], red[rb + 12 + k]));
            e[k] = mj ? __expf(l[k] - mm) : 0.f;
        }
        float s[4];
        #pragma unroll
        for (int k = 0; k < 4; ++k) {
            float v = e[k];
            #pragma unroll
            for (int off = 16; off; off >>= 1) v += __shfl_xor_sync(0xffffffffu, v, off);
            s[k] = v;
        }
        if (lane == 0) {
            #pragma unroll
            for (int k = 0; k < 4; ++k) red[64 + warp*4 + k] = s[k];
        }
    }
    __syncthreads();
    {
        int rb = 64 + half*16;
        #pragma unroll
        for (int k = 0; k < 4; ++k) {
            float ss = red[rb + k] + red[rb + 4 + k] + red[rb + 8 + k] + red[rb + 12 + k];
            float inv = (cnt > 0) ? (1.0f / ss) : 0.f;
            attn[c128*8 + half*4 + k] = e[k] * inv;
        }
    }
    __syncthreads();

    // ---- PASS 2: weighted hidden sum over 2 h-chunks; thread = (hl, pg: 2 i's) ----
    const float* WJb = g_WJ + b*NN*HH;
    const float* WIb = g_WI + rowbase*HH;
    {
        int hl = t & 63;
        int pg = t >> 6;    // 0..3 -> i pair pg*2, pg*2+1
        #pragma unroll
        for (int c = 0; c < 2; ++c) {
            // load WJ h-chunk
            #pragma unroll 8
            for (int idx = t; idx < 128*64; idx += 256) {
                int j = idx >> 6, hh = idx & 63;
                tab[j*65 + hh] = WJb[j*HH + c*64 + hh];
            }
            __syncthreads();
            int h = c*64 + hl;
            float wi0 = WIb[(pg*2    )*HH + h];
            float wi1 = WIb[(pg*2 + 1)*HH + h];
            float h0 = 0.f, h1 = 0.f;
            const float* tp = tab + hl;
            const float* ap = attn + pg*2;
            #pragma unroll 4
            for (int j = 0; j < NN; ++j) {
                float wv = tp[j*65];
                float2 at = *(const float2*)(ap + j*8);
                h0 = fmaf(at.x, fmaxf(wi0 + wv, 0.f), h0);
                h1 = fmaf(at.y, fmaxf(wi1 + wv, 0.f), h1);
            }
            hsb[(pg*2    )*128 + h] = h0;
            hsb[(pg*2 + 1)*128 + h] = h1;
            __syncthreads();
        }
    }

    // ---- UPDATE phases (overlay xr/aggs/us onto tab) ----
    float* xr   = tab;          // 512 floats [r][64]
    float* aggs = tab + 512;    // 1024 floats [r][128]
    float* us   = tab + 1536;   // 1024 floats [r][128]

    xr[t] = xreg0;
    xr[256 + t] = xreg1;

    // Phase A: agg[r][col] = hs[r] @ W2[:,col] + b2[col]*sa   (4 rows/thread)
    {
        float b2v = b2[c128];
        float acc[4];
        #pragma unroll
        for (int k = 0; k < 4; ++k) acc[k] = b2v * sa;
        const float4* W2T4 = (const float4*)g_W2T;
        const float4* hs4  = (const float4*)hsb;
        #pragma unroll 4
        for (int h4 = 0; h4 < 32; ++h4) {
            float4 wv = W2T4[h4*128 + c128];
            #pragma unroll
            for (int k = 0; k < 4; ++k) {
                float4 hv = hs4[(half*4 + k)*32 + h4];   // broadcast LDS
                acc[k] += hv.x*wv.x + hv.y*wv.y + hv.z*wv.z + hv.w*wv.w;
            }
        }
        #pragma unroll
        for (int k = 0; k < 4; ++k) aggs[(half*4 + k)*128 + c128] = acc[k];
    }
    __syncthreads();

    // Phase B: us[r][col] = relu([x_r, agg_r] @ U1[:,col] + ub1[col])
    {
        float ubv = ub1[c128];
        float u[4];
        #pragma unroll
        for (int k = 0; k < 4; ++k) u[k] = ubv;
        const float4* U1T4 = (const float4*)g_U1T;
        const float4* xr4  = (const float4*)xr;
        const float4* ag4  = (const float4*)aggs;
        #pragma unroll 4
        for (int c4 = 0; c4 < 48; ++c4) {
            float4 wv = U1T4[c4*128 + c128];
            #pragma unroll
            for (int k = 0; k < 4; ++k) {
                int r = half*4 + k;
                float4 cv = (c4 < 16) ? xr4[r*16 + c4] : ag4[r*32 + (c4-16)];
                u[k] += cv.x*wv.x + cv.y*wv.y + cv.z*wv.z + cv.w*wv.w;
            }
        }
        #pragma unroll
        for (int k = 0; k < 4; ++k) us[(half*4 + k)*128 + c128] = fmaxf(u[k], 0.f);
    }
    __syncthreads();

    // Phase C: out[r][col] = x[r][col] + us[r] @ U2[:,col] + ub2[col]  (2 rows/thread)
    {
        int col = t & 63;
        int rq  = t >> 6;            // 0..3 -> rows rq*2, rq*2+1
        float ub2v = ub2[col];
        float o0 = ub2v, o1 = ub2v;
        const float4* U2T4 = (const float4*)g_U2T;
        const float4* us4  = (const float4*)us;
        #pragma unroll 4
        for (int k4 = 0; k4 < 32; ++k4) {
            float4 wv = U2T4[k4*64 + col];
            float4 u0 = us4[(rq*2    )*32 + k4];   // broadcast
            float4 u1 = us4[(rq*2 + 1)*32 + k4];
            o0 += u0.x*wv.x + u0.y*wv.y + u0.z*wv.z + u0.w*wv.w;
            o1 += u1.x*wv.x + u1.y*wv.y + u1.z*wv.z + u1.w*wv.w;
        }
        int r0 = rq*2;
        out[(rowbase + r0    )*DD + col] = xr[r0*64 + col] + o0;
        out[(rowbase + r0 + 1)*DD + col] = xr[(r0+1)*64 + col] + o1;
    }
}

// ---------------- launch ----------------
extern "C" void kernel_launch(void* const* d_in, const int* in_sizes, int n_in,
                              void* d_out, int out_size) {
    const float* x    = (const float*)d_in[0];
    const int*   masks= (const int*)  d_in[1];
    const float* W1   = (const float*)d_in[2];
    const float* b1   = (const float*)d_in[3];
    const float* W2   = (const float*)d_in[4];
    const float* b2   = (const float*)d_in[5];
    const float* A1   = (const float*)d_in[6];
    const float* ab1  = (const float*)d_in[7];
    const float* A2   = (const float*)d_in[8];
    // d_in[9] = ab2: cancels in softmax
    const float* U1   = (const float*)d_in[10];
    const float* ub1  = (const float*)d_in[11];
    const float* U2   = (const float*)d_in[12];
    const float* ub2  = (const float*)d_in[13];
    float* out = (float*)d_out;

    cudaFuncSetAttribute(fused_kernel, cudaFuncAttributeMaxDynamicSharedMemorySize, SMEM_FUSED);

    prep_kernel<<<148, 256>>>(W1, W2, A1, U1, U2);
    proj_kernel<<<NROWS/8, 256>>>(x, b1, ab1);
    fused_kernel<<<BB*16, 256, SMEM_FUSED>>>(x, A2, masks, b2, ub1, ub2, out);
}

// round 5
// speedup vs baseline: 3.5859x; 1.2412x over previous
#include <cuda_runtime.h>

#define BB 32
#define NN 128
#define DD 64
#define HH 128
#define NROWS (BB*NN)   // 4096

// ---------------- scratch (device globals) ----------------
__device__ float g_AI[BB*NN*HH];   // x @ A1[:d]
__device__ float g_AJ[BB*NN*HH];   // x @ A1[d:] + ab1
__device__ float g_WI[BB*NN*HH];   // x @ W1[:d]
__device__ float g_WJ[BB*NN*HH];   // x @ W1[d:] + b1

// ---------------- per-node projections: 16 rows/block, direct weight reads ----------------
__global__ __launch_bounds__(256, 2)
void proj_kernel(const float* __restrict__ x,
                 const float* __restrict__ A1, const float* __restrict__ W1,
                 const float* __restrict__ b1, const float* __restrict__ ab1) {
    __shared__ __align__(16) float4 xr[16*16];   // 16 rows x 64 cols
    int t = threadIdx.x;
    int col = t & 127;
    int half = t >> 7;
    int row0 = blockIdx.x * 16;
    xr[t] = ((const float4*)x)[row0*16 + t];
    __syncthreads();
    float biasAJ = ab1[col];
    float biasWJ = b1[col];
    float a0[8], a1[8], a2[8], a3[8];
    #pragma unroll
    for (int r = 0; r < 8; ++r) { a0[r]=0.f; a1[r]=0.f; a2[r]=0.f; a3[r]=0.f; }
    #pragma unroll 2
    for (int d4 = 0; d4 < 16; ++d4) {
        // direct scalar weight reads (coalesced across col; L1-hot across blocks)
        float w0x = A1[(d4*4+0)*HH + col], w0y = A1[(d4*4+1)*HH + col];
        float w0z = A1[(d4*4+2)*HH + col], w0w = A1[(d4*4+3)*HH + col];
        float w1x = A1[(64+d4*4+0)*HH + col], w1y = A1[(64+d4*4+1)*HH + col];
        float w1z = A1[(64+d4*4+2)*HH + col], w1w = A1[(64+d4*4+3)*HH + col];
        float w2x = W1[(d4*4+0)*HH + col], w2y = W1[(d4*4+1)*HH + col];
        float w2z = W1[(d4*4+2)*HH + col], w2w = W1[(d4*4+3)*HH + col];
        float w3x = W1[(64+d4*4+0)*HH + col], w3y = W1[(64+d4*4+1)*HH + col];
        float w3z = W1[(64+d4*4+2)*HH + col], w3w = W1[(64+d4*4+3)*HH + col];
        #pragma unroll
        for (int r = 0; r < 8; ++r) {
            float4 xv = xr[(half*8 + r)*16 + d4];   // broadcast LDS
            a0[r] += xv.x*w0x + xv.y*w0y + xv.z*w0z + xv.w*w0w;
            a1[r] += xv.x*w1x + xv.y*w1y + xv.z*w1z + xv.w*w1w;
            a2[r] += xv.x*w2x + xv.y*w2y + xv.z*w2z + xv.w*w2w;
            a3[r] += xv.x*w3x + xv.y*w3y + xv.z*w3z + xv.w*w3w;
        }
    }
    #pragma unroll
    for (int r = 0; r < 8; ++r) {
        int row = row0 + half*8 + r;
        g_AI[row*HH + col] = a0[r];
        g_AJ[row*HH + col] = a1[r] + biasAJ;
        g_WI[row*HH + col] = a2[r];
        g_WJ[row*HH + col] = a3[r] + biasWJ;
    }
}

// ---------------- fused pair + update kernel: i-tile 16, 51.2KB smem ----------------
// 256 blocks (32 b x 8 i-tiles of 16), 256 threads, 3 blocks/SM cap -> single wave.
// SMEM floats:
//   tab : [0, 8320)       [j=128][hl=64] stride 65 (h-chunk of AJ / WJ);
//                         after pass2: xr[0..1024) aggs[1024..3072) us[3072..5120)
//   hsb : [8320, 10368)   pass1 aiT [h][16]  ->  pass2 output hs [r=16][128]
//   attn: [10368, 12416)  [j][16]
//   a2s : [12416, 12544)
//   red : [12544, 12672)  [half][4 warps][8 i] x {max, sum}
//   msk : [12672, 12800)  ints
#define SMF_FLOATS 12800
#define SMEM_FUSED (SMF_FLOATS * 4)
__global__ __launch_bounds__(256, 3)
void fused_kernel(const float* __restrict__ x, const float* __restrict__ A2,
                  const int* __restrict__ masks,
                  const float* __restrict__ W2, const float* __restrict__ b2,
                  const float* __restrict__ U1, const float* __restrict__ ub1,
                  const float* __restrict__ U2, const float* __restrict__ ub2,
                  float* __restrict__ out) {
    extern __shared__ __align__(16) float sm[];
    float* tab  = sm;
    float* hsb  = sm + 8320;    // aiT during pass1, hs after pass2
    float* attn = sm + 10368;
    float* a2s  = sm + 12416;
    float* red  = sm + 12544;
    int*   msk  = (int*)(sm + 12672);

    int t = threadIdx.x;
    int c128 = t & 127;
    int half = t >> 7;          // 0/1
    int warp = t >> 5, lane = t & 31;
    int wl = warp & 3;          // warp within half
    int b  = blockIdx.x >> 3;
    int i0 = (blockIdx.x & 7) * 16;
    int rowbase = b*NN + i0;

    // preload x tile into registers (16 rows x 64 = 1024 floats)
    float xreg[4];
    #pragma unroll
    for (int k = 0; k < 4; ++k) xreg[k] = x[rowbase*DD + k*256 + t];

    if (t < 128) { a2s[t] = A2[t]; msk[t] = masks[b*NN + t]; }

    // aiT[h=c128][ii] for this half's 8 i's
    const float* AIb = g_AI + rowbase*HH;
    #pragma unroll
    for (int k = 0; k < 8; ++k)
        hsb[c128*16 + half*8 + k] = AIb[(half*8 + k)*HH + c128];

    int cnt = __syncthreads_count(msk[c128] != 0);
    float sa = (cnt > 0) ? 1.0f : 0.0f;
    bool mj = msk[c128] != 0;

    // ---- PASS 1: logits over 2 h-chunks; thread = (j=c128, half: 8 i's) ----
    float l[8];
    #pragma unroll
    for (int k = 0; k < 8; ++k) l[k] = 0.f;
    const float* AJb = g_AJ + b*NN*HH;
    #pragma unroll
    for (int c = 0; c < 2; ++c) {
        #pragma unroll 8
        for (int idx = t; idx < 128*64; idx += 256) {
            int j = idx >> 6, hl = idx & 63;
            tab[j*65 + hl] = AJb[j*HH + c*64 + hl];
        }
        __syncthreads();
        const float* tp = tab + c128*65;
        #pragma unroll 4
        for (int hl = 0; hl < 64; ++hl) {
            int h = c*64 + hl;
            float av  = tp[hl];
            float a2v = a2s[h];
            float4 s0 = *(const float4*)(hsb + h*16 + half*8);
            float4 s1 = *(const float4*)(hsb + h*16 + half*8 + 4);
            l[0] = fmaf(fmaxf(av + s0.x, 0.f), a2v, l[0]);
            l[1] = fmaf(fmaxf(av + s0.y, 0.f), a2v, l[1]);
            l[2] = fmaf(fmaxf(av + s0.z, 0.f), a2v, l[2]);
            l[3] = fmaf(fmaxf(av + s0.w, 0.f), a2v, l[3]);
            l[4] = fmaf(fmaxf(av + s1.x, 0.f), a2v, l[4]);
            l[5] = fmaf(fmaxf(av + s1.y, 0.f), a2v, l[5]);
            l[6] = fmaf(fmaxf(av + s1.z, 0.f), a2v, l[6]);
            l[7] = fmaf(fmaxf(av + s1.w, 0.f), a2v, l[7]);
        }
        __syncthreads();
    }
    if (!mj) {
        #pragma unroll
        for (int k = 0; k < 8; ++k) l[k] = -1e30f;
    }
    // block-max per i (reduce over j within each half: 4 warps)
    {
        #pragma unroll
        for (int k = 0; k < 8; ++k) {
            float v = l[k];
            #pragma unroll
            for (int off = 16; off; off >>= 1) v = fmaxf(v, __shfl_xor_sync(0xffffffffu, v, off));
            if (lane == 0) red[(half*4 + wl)*8 + k] = v;
        }
    }
    __syncthreads();
    float e[8];
    {
        const float* rb = red + half*32;
        #pragma unroll
        for (int k = 0; k < 8; ++k) {
            float mm = fmaxf(fmaxf(rb[k], rb[8+k]), fmaxf(rb[16+k], rb[24+k]));
            e[k] = mj ? __expf(l[k] - mm) : 0.f;
        }
        #pragma unroll
        for (int k = 0; k < 8; ++k) {
            float v = e[k];
            #pragma unroll
            for (int off = 16; off; off >>= 1) v += __shfl_xor_sync(0xffffffffu, v, off);
            if (lane == 0) red[64 + (half*4 + wl)*8 + k] = v;
        }
    }
    __syncthreads();
    {
        const float* rb = red + 64 + half*32;
        #pragma unroll
        for (int k = 0; k < 8; ++k) {
            float ss = rb[k] + rb[8+k] + rb[16+k] + rb[24+k];
            float inv = (cnt > 0) ? (1.0f / ss) : 0.f;
            attn[c128*16 + half*8 + k] = e[k] * inv;
        }
    }
    __syncthreads();

    // ---- PASS 2: weighted hidden sum over 2 h-chunks; thread = (hl, pg: 4 i's) ----
    const float* WJb = g_WJ + b*NN*HH;
    const float* WIb = g_WI + rowbase*HH;
    {
        int hl = t & 63;
        int pg = t >> 6;    // 0..3 -> i group pg*4 .. pg*4+3
        #pragma unroll
        for (int c = 0; c < 2; ++c) {
            #pragma unroll 8
            for (int idx = t; idx < 128*64; idx += 256) {
                int j = idx >> 6, hh = idx & 63;
                tab[j*65 + hh] = WJb[j*HH + c*64 + hh];
            }
            __syncthreads();
            int h = c*64 + hl;
            float wi0 = WIb[(pg*4    )*HH + h];
            float wi1 = WIb[(pg*4 + 1)*HH + h];
            float wi2 = WIb[(pg*4 + 2)*HH + h];
            float wi3 = WIb[(pg*4 + 3)*HH + h];
            float h0 = 0.f, h1 = 0.f, h2 = 0.f, h3 = 0.f;
            const float* tp = tab + hl;
            const float* ap = attn + pg*4;
            #pragma unroll 4
            for (int j = 0; j < NN; ++j) {
                float wv = tp[j*65];
                float4 at = *(const float4*)(ap + j*16);   // broadcast LDS.128
                h0 = fmaf(at.x, fmaxf(wi0 + wv, 0.f), h0);
                h1 = fmaf(at.y, fmaxf(wi1 + wv, 0.f), h1);
                h2 = fmaf(at.z, fmaxf(wi2 + wv, 0.f), h2);
                h3 = fmaf(at.w, fmaxf(wi3 + wv, 0.f), h3);
            }
            hsb[(pg*4    )*128 + h] = h0;
            hsb[(pg*4 + 1)*128 + h] = h1;
            hsb[(pg*4 + 2)*128 + h] = h2;
            hsb[(pg*4 + 3)*128 + h] = h3;
            __syncthreads();
        }
    }

    // ---- UPDATE phases (overlay xr/aggs/us onto tab) ----
    float* xr   = tab;          // 1024 floats [r=16][64]
    float* aggs = tab + 1024;   // 2048 floats [r][128]
    float* us   = tab + 3072;   // 2048 floats [r][128]

    #pragma unroll
    for (int k = 0; k < 4; ++k) xr[k*256 + t] = xreg[k];

    // Phase A: agg[r][col] = hs[r] @ W2[:,col] + b2[col]*sa   (8 rows/thread, direct W2)
    {
        float b2v = b2[c128];
        float acc[8];
        #pragma unroll
        for (int k = 0; k < 8; ++k) acc[k] = b2v * sa;
        const float4* hs4 = (const float4*)hsb;
        #pragma unroll 4
        for (int h4 = 0; h4 < 32; ++h4) {
            float wx = W2[(h4*4+0)*HH + c128];
            float wy = W2[(h4*4+1)*HH + c128];
            float wz = W2[(h4*4+2)*HH + c128];
            float ww = W2[(h4*4+3)*HH + c128];
            #pragma unroll
            for (int k = 0; k < 8; ++k) {
                float4 hv = hs4[(half*8 + k)*32 + h4];   // broadcast LDS
                acc[k] += hv.x*wx + hv.y*wy + hv.z*wz + hv.w*ww;
            }
        }
        #pragma unroll
        for (int k = 0; k < 8; ++k) aggs[(half*8 + k)*128 + c128] = acc[k];
    }
    __syncthreads();

    // Phase B: us[r][col] = relu([x_r, agg_r] @ U1[:,col] + ub1[col])
    {
        float ubv = ub1[c128];
        float u[8];
        #pragma unroll
        for (int k = 0; k < 8; ++k) u[k] = ubv;
        const float4* xr4 = (const float4*)xr;
        const float4* ag4 = (const float4*)aggs;
        #pragma unroll 4
        for (int c4 = 0; c4 < 48; ++c4) {
            float wx = U1[(c4*4+0)*HH + c128];
            float wy = U1[(c4*4+1)*HH + c128];
            float wz = U1[(c4*4+2)*HH + c128];
            float ww = U1[(c4*4+3)*HH + c128];
            #pragma unroll
            for (int k = 0; k < 8; ++k) {
                int r = half*8 + k;
                float4 cv = (c4 < 16) ? xr4[r*16 + c4] : ag4[r*32 + (c4-16)];
                u[k] += cv.x*wx + cv.y*wy + cv.z*wz + cv.w*ww;
            }
        }
        #pragma unroll
        for (int k = 0; k < 8; ++k) us[(half*8 + k)*128 + c128] = fmaxf(u[k], 0.f);
    }
    __syncthreads();

    // Phase C: out[r][col] = x[r][col] + us[r] @ U2[:,col] + ub2[col]  (4 rows/thread)
    {
        int col = t & 63;
        int rq  = t >> 6;            // 0..3 -> rows rq*4 .. rq*4+3
        float ub2v = ub2[col];
        float o[4];
        #pragma unroll
        for (int k = 0; k < 4; ++k) o[k] = ub2v;
        const float4* us4 = (const float4*)us;
        #pragma unroll 4
        for (int k4 = 0; k4 < 32; ++k4) {
            float wx = U2[(k4*4+0)*DD + col];
            float wy = U2[(k4*4+1)*DD + col];
            float wz = U2[(k4*4+2)*DD + col];
            float ww = U2[(k4*4+3)*DD + col];
            #pragma unroll
            for (int k = 0; k < 4; ++k) {
                float4 uv = us4[(rq*4 + k)*32 + k4];   // broadcast
                o[k] += uv.x*wx + uv.y*wy + uv.z*wz + uv.w*ww;
            }
        }
        #pragma unroll
        for (int k = 0; k < 4; ++k) {
            int r = rq*4 + k;
            out[(rowbase + r)*DD + col] = xr[r*64 + col] + o[k];
        }
    }
}

// ---------------- launch ----------------
extern "C" void kernel_launch(void* const* d_in, const int* in_sizes, int n_in,
                              void* d_out, int out_size) {
    const float* x    = (const float*)d_in[0];
    const int*   masks= (const int*)  d_in[1];
    const float* W1   = (const float*)d_in[2];
    const float* b1   = (const float*)d_in[3];
    const float* W2   = (const float*)d_in[4];
    const float* b2   = (const float*)d_in[5];
    const float* A1   = (const float*)d_in[6];
    const float* ab1  = (const float*)d_in[7];
    const float* A2   = (const float*)d_in[8];
    // d_in[9] = ab2: cancels in softmax
    const float* U1   = (const float*)d_in[10];
    const float* ub1  = (const float*)d_in[11];
    const float* U2   = (const float*)d_in[12];
    const float* ub2  = (const float*)d_in[13];
    float* out = (float*)d_out;

    cudaFuncSetAttribute(fused_kernel, cudaFuncAttributeMaxDynamicSharedMemorySize, SMEM_FUSED);

    proj_kernel<<<NROWS/16, 256>>>(x, A1, W1, b1, ab1);
    fused_kernel<<<BB*8, 256, SMEM_FUSED>>>(x, A2, masks, W2, b2, U1, ub1, U2, ub2, out);
}